// round 13
// baseline (speedup 1.0000x reference)
#include <cuda_runtime.h>
#include <cuda_bf16.h>
#include <cstdint>
#include <cstddef>

#define NROWS 8192
#define INDIM 2029
#define HW 2112   // padded plane width: 128(T) + 384(A) + 1600(V)

// Scratch (device globals — no allocation allowed)
__device__ __align__(16) __nv_bfloat16 g_h_hi[NROWS * HW];
__device__ __align__(16) __nv_bfloat16 g_h_lo[NROWS * HW];
__device__ __align__(16) __nv_bfloat16 g_ws[9 * 128 * 4800];   // per-seg B' = [bh|bh|bl]
__device__ __align__(16) __nv_bfloat16 g_wln[128 * 1152];      // Wln B' = [bh|bh|bl]
__device__ float g_qkv[NROWS * 1152];                          // [n][Vq Vk Vv Aq Ak Av Tq Tk Tv]
__device__ float g_qkv2[NROWS * 384];                          // V segs, K-chunks [38,75) partial
__device__ __align__(16) __nv_bfloat16 g_att_hi[NROWS * 384];  // [n][T|A|V] hi
__device__ __align__(16) __nv_bfloat16 g_att_lo[NROWS * 384];  // [n][T|A|V] lo

struct WPtrs { const float* w[9]; };

__device__ __forceinline__ float ex2f(float x) {
    float r; asm("ex2.approx.f32 %0, %1;" : "=f"(r) : "f"(x)); return r;
}
__device__ __forceinline__ uint32_t smem_u32(const void* p) {
    uint32_t a;
    asm("{ .reg .u64 t; cvta.to.shared.u64 t, %1; cvt.u32.u64 %0, t; }" : "=r"(a) : "l"(p));
    return a;
}
__device__ __forceinline__ void mma16816(float* c, const uint32_t* a, const uint32_t* b) {
    asm volatile(
        "mma.sync.aligned.m16n8k16.row.col.f32.bf16.bf16.f32 "
        "{%0,%1,%2,%3}, {%4,%5,%6,%7}, {%8,%9}, {%0,%1,%2,%3};"
        : "+f"(c[0]), "+f"(c[1]), "+f"(c[2]), "+f"(c[3])
        : "r"(a[0]), "r"(a[1]), "r"(a[2]), "r"(a[3]), "r"(b[0]), "r"(b[1]));
}
__device__ __forceinline__ void ldsm_x4(uint32_t* r, uint32_t addr) {
    asm volatile("ldmatrix.sync.aligned.m8n8.x4.shared.b16 {%0,%1,%2,%3}, [%4];"
        : "=r"(r[0]), "=r"(r[1]), "=r"(r[2]), "=r"(r[3]) : "r"(addr));
}
__device__ __forceinline__ void cp16(uint32_t d, const void* s) {
    asm volatile("cp.async.cg.shared.global [%0], [%1], 16;" :: "r"(d), "l"(s));
}
__device__ __forceinline__ void cp_commit() { asm volatile("cp.async.commit_group;" ::: "memory"); }
__device__ __forceinline__ void cp_wait1()  { asm volatile("cp.async.wait_group 1;" ::: "memory"); }

// ---------------------------------------------------------------------------
// Precompute: h -> per-unit hi/lo bf16 planes (zero-padded widths 128/384/1600)
// 4 cols per thread; STG.64 stores.
// ---------------------------------------------------------------------------
__global__ __launch_bounds__(256)
void conv_h_kernel(const float* __restrict__ h) {
    const int n = blockIdx.x;
    const float* hrow = h + (size_t)n * INDIM;
    for (int g = threadIdx.x; g < HW / 4; g += 256) {
        const int col = g * 4;
        int off, local0, F;
        if (col < 128)      { off = 0;   local0 = col;       F = 100; }
        else if (col < 512) { off = 100; local0 = col - 128; F = 342; }
        else                { off = 442; local0 = col - 512; F = 1587; }
        __nv_bfloat16 hi4[4], lo4[4];
#pragma unroll
        for (int e = 0; e < 4; e++) {
            int lc = local0 + e;
            float v = (lc < F) ? __ldg(hrow + off + lc) : 0.0f;
            __nv_bfloat16 hi = __float2bfloat16(v);
            hi4[e] = hi;
            lo4[e] = __float2bfloat16(v - __bfloat162float(hi));
        }
        *reinterpret_cast<uint2*>(&g_h_hi[(size_t)n * HW + col]) = *reinterpret_cast<uint2*>(hi4);
        *reinterpret_cast<uint2*>(&g_h_lo[(size_t)n * HW + col]) = *reinterpret_cast<uint2*>(lo4);
    }
}

// ---------------------------------------------------------------------------
// Precompute weights: B' = [bh | bh | bl] per seg (and Wln as seg 9)
// ---------------------------------------------------------------------------
__global__ __launch_bounds__(256)
void conv_w_kernel(WPtrs wp, const float* __restrict__ Wln) {
    const int Fs[10]  = {1587,1587,1587, 342,342,342, 100,100,100, 384};
    const int Fps[10] = {1600,1600,1600, 384,384,384, 128,128,128, 384};
    const int d = blockIdx.x, t = blockIdx.y;
    const int F = Fs[t], Fp = Fps[t];
    const float* W = (t < 9) ? wp.w[t] : Wln;
    __nv_bfloat16* dst = (t < 9) ? (g_ws + (size_t)t * 128 * 4800 + (size_t)d * 3 * Fp)
                                 : (g_wln + (size_t)d * 1152);
    for (int k = threadIdx.x; k < 3 * Fp; k += 256) {
        int p = k / Fp, col = k - p * Fp;
        float v = (col < F) ? __ldg(W + (size_t)d * F + col) : 0.0f;
        __nv_bfloat16 hi = __float2bfloat16(v);
        if (p == 2) dst[k] = __float2bfloat16(v - __bfloat162float(hi));
        else        dst[k] = hi;
    }
}

// ---------------------------------------------------------------------------
// Plain bf16 GEMM, 512 threads: C[128 x 128] = A'[128 x 3Kp] * B'[128 x 3Kp]^T
// (+ bias), over chunk range [c0, c1). A' planes: [hi | lo | hi] (selected in
// loader); B' physically [bh|bh|bl]. 16 warps, warp tile 32x32 (acc = 32 regs).
// cp.async 3-stage pipeline, ldmatrix fragments, smem row stride 144B.
// ---------------------------------------------------------------------------
#define ROWB 144
#define TILEB (128 * ROWB)
#define STAGEB (2 * TILEB)
#define GEMM_SMEM (3 * STAGEB)   // 110592

__device__ __forceinline__ void gemm_bf16_128(
    const __nv_bfloat16* __restrict__ Ahi, const __nv_bfloat16* __restrict__ Alo,
    int sA, int Kp,
    const __nv_bfloat16* __restrict__ B, int ldb,
    float* __restrict__ C, int ldc, const float* __restrict__ bias, int n0,
    int c0, int c1)
{
    extern __shared__ __align__(16) char dsm[];
    const uint32_t sbase = smem_u32(dsm);
    const int tid = threadIdx.x;
    const int lane = tid & 31, wid = tid >> 5;       // 16 warps
    const int wm = wid & 3, wn = wid >> 2;           // 4 x 4 warp grid
    const int g4 = lane >> 2, tq = lane & 3;
    const int lr = tid >> 2;                          // loader row 0..127
    const int q4 = tid & 3;                           // loader quarter

    const int Kc = Kp >> 6;      // 64-wide chunks per plane
    const int NC = c1 - c0;

    // ldmatrix lane-address components (x4: rows of two 8x8 pairs + klo/khi)
    const uint32_t a_off = (uint32_t)(wm * 32 + ((lane >> 3) & 1) * 8 + (lane & 7)) * ROWB
                           + ((lane >> 4) & 1) * 16;
    const uint32_t b_off = (uint32_t)(wn * 32 + ((lane >> 4) & 1) * 8 + (lane & 7)) * ROWB
                           + ((lane >> 3) & 1) * 16;

    float acc[2][4][4];
#pragma unroll
    for (int t = 0; t < 2; t++)
#pragma unroll
        for (int nt = 0; nt < 4; nt++)
#pragma unroll
            for (int i = 0; i < 4; i++) acc[t][nt][i] = 0.0f;

    auto issue = [&](int c, int st) {
        int pk = c / Kc;
        int cb = (c - pk * Kc) << 6;
        const __nv_bfloat16* As = ((pk == 1) ? Alo : Ahi)
                                  + (size_t)(n0 + lr) * sA + cb + q4 * 16;
        const __nv_bfloat16* Bs = B + (size_t)lr * ldb + (c << 6) + q4 * 16;
        uint32_t ab = sbase + st * STAGEB + lr * ROWB + q4 * 32;
        uint32_t bb = ab + TILEB;
#pragma unroll
        for (int i = 0; i < 2; i++) {
            cp16(ab + i * 16, As + i * 8);
            cp16(bb + i * 16, Bs + i * 8);
        }
        cp_commit();
    };

    issue(c0, 0);
    if (NC > 1) issue(c0 + 1, 1); else cp_commit();

    for (int ci = 0; ci < NC; ci++) {
        cp_wait1();
        __syncthreads();

        const uint32_t sa = sbase + (ci % 3) * STAGEB;
        const uint32_t aaddr = sa + a_off;
        const uint32_t baddr = sa + TILEB + b_off;
#pragma unroll
        for (int kk = 0; kk < 4; kk++) {
            uint32_t a[2][4], b[2][4];
            ldsm_x4(a[0], aaddr + kk * 32);
            ldsm_x4(a[1], aaddr + 16 * ROWB + kk * 32);
            ldsm_x4(b[0], baddr + kk * 32);
            ldsm_x4(b[1], baddr + 16 * ROWB + kk * 32);
#pragma unroll
            for (int nt = 0; nt < 4; nt++) {
                mma16816(acc[0][nt], a[0], b[nt >> 1] + (nt & 1) * 2);
                mma16816(acc[1][nt], a[1], b[nt >> 1] + (nt & 1) * 2);
            }
        }

        if (ci + 2 < NC) issue(c0 + ci + 2, (ci + 2) % 3);
        else cp_commit();   // empty group keeps wait_group bookkeeping consistent
    }

#pragma unroll
    for (int t = 0; t < 2; t++)
#pragma unroll
        for (int nt = 0; nt < 4; nt++) {
            int gm = n0 + wm * 32 + t * 16 + g4;
            int gn = wn * 32 + nt * 8 + tq * 2;
            float bx = 0.0f, by = 0.0f;
            if (bias) { bx = __ldg(bias + gn); by = __ldg(bias + gn + 1); }
            float2 v0 = make_float2(acc[t][nt][0] + bx, acc[t][nt][1] + by);
            float2 v1 = make_float2(acc[t][nt][2] + bx, acc[t][nt][3] + by);
            *(float2*)(C + (size_t)gm * ldc + gn) = v0;
            *(float2*)(C + (size_t)(gm + 8) * ldc + gn) = v1;
        }
}

// ---------------------------------------------------------------------------
// Kernel 1: QKV projections. V segs (s<3) split in K over blockIdx.z:
// z=0 -> chunks [0,38) into g_qkv; z=1 -> chunks [38,75) into g_qkv2.
// ---------------------------------------------------------------------------
__global__ __launch_bounds__(512, 2)
void qkv_mma_kernel() {
    const int Fps[9] = {1600,1600,1600, 384,384,384, 128,128,128};
    const int ub[9]  = { 512, 512, 512, 128,128,128,   0,  0,  0};
    const int s = blockIdx.y, z = blockIdx.z;
    const int Fp = Fps[s];
    const int NC = 3 * (Fp >> 6);

    int c0 = 0, c1 = NC, ldc = 1152;
    float* C = g_qkv + s * 128;
    if (s < 3) {
        if (z == 0) c1 = 38;
        else { c0 = 38; C = g_qkv2 + s * 128; ldc = 384; }
    } else if (z == 1) {
        return;
    }
    gemm_bf16_128(g_h_hi + ub[s], g_h_lo + ub[s], HW, Fp,
                  g_ws + (size_t)s * 128 * 4800, 3 * Fp,
                  C, ldc, nullptr, blockIdx.x * 128, c0, c1);
}

// ---------------------------------------------------------------------------
// Kernel 2: fused attention, one 512-thread block per (n, u).
// 16 warps = (4 row-stripes) x (4 col-quarters); each warp runs the
// register-resident XOR-butterfly on its 32x32 E block. Z assembled across
// stripes in smem; quarter partials summed in smem; block writes att hi/lo
// planes directly (no g_attp round trip, no fixup kernel).
// ---------------------------------------------------------------------------
__global__ __launch_bounds__(512)
void attn_kernel() {
    __shared__ float zp[4][128];   // [stripe][col]   column-Z partials
    __shared__ float op[4][128];   // [quarter][row]  row-output partials

    const int n = blockIdx.x;
    const int u = blockIdx.y;      // 0=V, 1=A, 2=T (qkv seg order)
    const int t    = threadIdx.x;
    const int lane = t & 31;
    const int w    = t >> 5;       // 16 warps
    const int ih   = w & 3;        // row stripe  [ih*32, +32)
    const int jq   = w >> 2;       // col quarter [jq*32, +32)

    const float* base  = g_qkv  + (size_t)n * 1152 + u * 384;
    const float* base2 = g_qkv2 + (size_t)n * 384;

    // log2(e) / sqrt(128)
    const float scale = 1.4426950408889634f / 11.313708498984761f;
    const int qi_idx = ih * 32 + lane;    // this lane's row
    const int kj_idx = jq * 32 + lane;    // this lane's column
    float qraw = base[qi_idx];
    float kraw = base[128 + kj_idx];
    float vraw = base[256 + kj_idx];
    if (u == 0) {
        qraw += base2[qi_idx];
        kraw += base2[128 + kj_idx];
        vraw += base2[256 + kj_idx];
    }
    const float qown = qraw * scale;

    // Phase 1: c[s] = E[stripe row (lane^s)][col lane], lane-local column Z.
    float c[32];
    float z = 0.0f;
#pragma unroll
    for (int s = 0; s < 32; s++) {
        float qi = __shfl_xor_sync(0xFFFFFFFFu, qown, s);
        float e = ex2f(qi * kraw);
        c[s] = e;
        z += e;
    }
    zp[ih][kj_idx] = z;
    __syncthreads();

    // Column Z over all 4 stripes; lane-local w_j = v_j / Z_j
    float Z = (zp[0][kj_idx] + zp[1][kj_idx]) + (zp[2][kj_idx] + zp[3][kj_idx]);
    const float ws = vraw / Z;

    // Phase 2: butterfly transpose-sum -> row partial over this quarter.
    float out = 0.0f;
#pragma unroll
    for (int s = 0; s < 32; s++) {
        out += __shfl_xor_sync(0xFFFFFFFFu, c[s] * ws, s);
    }
    op[jq][qi_idx] = out;
    __syncthreads();

    // Sum quarter partials, emit att hi/lo bf16 planes directly.
    if (t < 128) {
        float o = (op[0][t] + op[1][t]) + (op[2][t] + op[3][t]);
        const int attoff = (2 - u) * 128;   // att layout [T|A|V]
        __nv_bfloat16 hi = __float2bfloat16(o);
        g_att_hi[(size_t)n * 384 + attoff + t] = hi;
        g_att_lo[(size_t)n * 384 + attoff + t] = __float2bfloat16(o - __bfloat162float(hi));
    }
}

// ---------------------------------------------------------------------------
// Kernel 3: out = att @ Wln.T + bln (plain bf16 GEMM, K' = 1152)
// ---------------------------------------------------------------------------
__global__ __launch_bounds__(512, 2)
void out_mma_kernel(const float* __restrict__ bln, float* __restrict__ out) {
    gemm_bf16_128(g_att_hi, g_att_lo, 384, 384, g_wln, 1152,
                  out, 128, bln, blockIdx.x * 128, 0, 18);
}

// ---------------------------------------------------------------------------
// Input order: 0 g, 1 h, 2 WqT, 3 WkT, 4 WvT, 5 WqA, 6 WkA, 7 WvA,
//              8 WqV, 9 WkV, 10 WvV, 11 Wln, 12 bln
// ---------------------------------------------------------------------------
extern "C" void kernel_launch(void* const* d_in, const int* in_sizes, int n_in,
                              void* d_out, int out_size) {
    const float* h = (const float*)d_in[1];
    WPtrs wp;
    wp.w[0] = (const float*)d_in[8];   // WqV
    wp.w[1] = (const float*)d_in[9];   // WkV
    wp.w[2] = (const float*)d_in[10];  // WvV
    wp.w[3] = (const float*)d_in[5];   // WqA
    wp.w[4] = (const float*)d_in[6];   // WkA
    wp.w[5] = (const float*)d_in[7];   // WvA
    wp.w[6] = (const float*)d_in[2];   // WqT
    wp.w[7] = (const float*)d_in[3];   // WkT
    wp.w[8] = (const float*)d_in[4];   // WvT
    const float* Wln = (const float*)d_in[11];
    const float* bln = (const float*)d_in[12];

    conv_h_kernel<<<NROWS, 256>>>(h);
    conv_w_kernel<<<dim3(128, 10), 256>>>(wp, Wln);

    cudaFuncSetAttribute(qkv_mma_kernel, cudaFuncAttributeMaxDynamicSharedMemorySize,
                         GEMM_SMEM);
    qkv_mma_kernel<<<dim3(64, 9, 2), 512, GEMM_SMEM>>>();

    attn_kernel<<<dim3(NROWS, 3), 512>>>();

    cudaFuncSetAttribute(out_mma_kernel, cudaFuncAttributeMaxDynamicSharedMemorySize,
                         GEMM_SMEM);
    out_mma_kernel<<<64, 512, GEMM_SMEM>>>(bln, (float*)d_out);
}

// round 14
// speedup vs baseline: 1.1039x; 1.1039x over previous
#include <cuda_runtime.h>
#include <cuda_bf16.h>
#include <cstdint>
#include <cstddef>

#define NROWS 8192
#define INDIM 2029
#define HW 2112   // padded plane width: 128(T) + 384(A) + 1600(V)

// Scratch (device globals — no allocation allowed)
__device__ __align__(16) __nv_bfloat16 g_h_hi[NROWS * HW];
__device__ __align__(16) __nv_bfloat16 g_h_lo[NROWS * HW];
__device__ __align__(16) __nv_bfloat16 g_ws[9 * 128 * 4800];   // per-seg B' = [bh|bh|bl]
__device__ __align__(16) __nv_bfloat16 g_wln[128 * 1152];      // Wln B' = [bh|bh|bl]
__device__ float g_qkv[NROWS * 1152];                          // [n][Vq Vk Vv Aq Ak Av Tq Tk Tv]
__device__ float g_qkv2[NROWS * 384];                          // V segs, K-chunks [38,75) partial
__device__ __align__(16) __nv_bfloat16 g_att_hi[NROWS * 384];  // [n][T|A|V] hi
__device__ __align__(16) __nv_bfloat16 g_att_lo[NROWS * 384];  // [n][T|A|V] lo

struct WPtrs { const float* w[9]; };

__device__ __forceinline__ float ex2f(float x) {
    float r; asm("ex2.approx.f32 %0, %1;" : "=f"(r) : "f"(x)); return r;
}
__device__ __forceinline__ uint32_t smem_u32(const void* p) {
    uint32_t a;
    asm("{ .reg .u64 t; cvta.to.shared.u64 t, %1; cvt.u32.u64 %0, t; }" : "=r"(a) : "l"(p));
    return a;
}
__device__ __forceinline__ void mma16816(float* c, const uint32_t* a, const uint32_t* b) {
    asm volatile(
        "mma.sync.aligned.m16n8k16.row.col.f32.bf16.bf16.f32 "
        "{%0,%1,%2,%3}, {%4,%5,%6,%7}, {%8,%9}, {%0,%1,%2,%3};"
        : "+f"(c[0]), "+f"(c[1]), "+f"(c[2]), "+f"(c[3])
        : "r"(a[0]), "r"(a[1]), "r"(a[2]), "r"(a[3]), "r"(b[0]), "r"(b[1]));
}
__device__ __forceinline__ void ldsm_x4(uint32_t* r, uint32_t addr) {
    asm volatile("ldmatrix.sync.aligned.m8n8.x4.shared.b16 {%0,%1,%2,%3}, [%4];"
        : "=r"(r[0]), "=r"(r[1]), "=r"(r[2]), "=r"(r[3]) : "r"(addr));
}
__device__ __forceinline__ void cp16(uint32_t d, const void* s) {
    asm volatile("cp.async.cg.shared.global [%0], [%1], 16;" :: "r"(d), "l"(s));
}
__device__ __forceinline__ void cp_commit() { asm volatile("cp.async.commit_group;" ::: "memory"); }
__device__ __forceinline__ void cp_wait1()  { asm volatile("cp.async.wait_group 1;" ::: "memory"); }

// ---------------------------------------------------------------------------
// Precompute: h -> per-unit hi/lo bf16 planes (zero-padded widths 128/384/1600)
// 4 cols per thread; STG.64 stores.
// ---------------------------------------------------------------------------
__global__ __launch_bounds__(256)
void conv_h_kernel(const float* __restrict__ h) {
    const int n = blockIdx.x;
    const float* hrow = h + (size_t)n * INDIM;
    for (int g = threadIdx.x; g < HW / 4; g += 256) {
        const int col = g * 4;
        int off, local0, F;
        if (col < 128)      { off = 0;   local0 = col;       F = 100; }
        else if (col < 512) { off = 100; local0 = col - 128; F = 342; }
        else                { off = 442; local0 = col - 512; F = 1587; }
        __nv_bfloat16 hi4[4], lo4[4];
#pragma unroll
        for (int e = 0; e < 4; e++) {
            int lc = local0 + e;
            float v = (lc < F) ? __ldg(hrow + off + lc) : 0.0f;
            __nv_bfloat16 hi = __float2bfloat16(v);
            hi4[e] = hi;
            lo4[e] = __float2bfloat16(v - __bfloat162float(hi));
        }
        *reinterpret_cast<uint2*>(&g_h_hi[(size_t)n * HW + col]) = *reinterpret_cast<uint2*>(hi4);
        *reinterpret_cast<uint2*>(&g_h_lo[(size_t)n * HW + col]) = *reinterpret_cast<uint2*>(lo4);
    }
}

// ---------------------------------------------------------------------------
// Precompute weights: B' = [bh | bh | bl] per seg (and Wln as seg 9)
// ---------------------------------------------------------------------------
__global__ __launch_bounds__(256)
void conv_w_kernel(WPtrs wp, const float* __restrict__ Wln) {
    const int Fs[10]  = {1587,1587,1587, 342,342,342, 100,100,100, 384};
    const int Fps[10] = {1600,1600,1600, 384,384,384, 128,128,128, 384};
    const int d = blockIdx.x, t = blockIdx.y;
    const int F = Fs[t], Fp = Fps[t];
    const float* W = (t < 9) ? wp.w[t] : Wln;
    __nv_bfloat16* dst = (t < 9) ? (g_ws + (size_t)t * 128 * 4800 + (size_t)d * 3 * Fp)
                                 : (g_wln + (size_t)d * 1152);
    for (int k = threadIdx.x; k < 3 * Fp; k += 256) {
        int p = k / Fp, col = k - p * Fp;
        float v = (col < F) ? __ldg(W + (size_t)d * F + col) : 0.0f;
        __nv_bfloat16 hi = __float2bfloat16(v);
        if (p == 2) dst[k] = __float2bfloat16(v - __bfloat162float(hi));
        else        dst[k] = hi;
    }
}

// ---------------------------------------------------------------------------
// Plain bf16 GEMM, 512 threads: C[128 x 128] = A'[128 x 3Kp] * B'[128 x 3Kp]^T
// (+ bias), over chunk range [c0, c1). A' planes: [hi | lo | hi] (selected in
// loader); B' physically [bh|bh|bl]. 16 warps, warp tile 32x32 (acc = 32 regs).
// cp.async 3-stage pipeline, ldmatrix fragments, smem row stride 144B.
// ---------------------------------------------------------------------------
#define ROWB 144
#define TILEB (128 * ROWB)
#define STAGEB (2 * TILEB)
#define GEMM_SMEM (3 * STAGEB)   // 110592

__device__ __forceinline__ void gemm_bf16_128(
    const __nv_bfloat16* __restrict__ Ahi, const __nv_bfloat16* __restrict__ Alo,
    int sA, int Kp,
    const __nv_bfloat16* __restrict__ B, int ldb,
    float* __restrict__ C, int ldc, const float* __restrict__ bias, int n0,
    int c0, int c1)
{
    extern __shared__ __align__(16) char dsm[];
    const uint32_t sbase = smem_u32(dsm);
    const int tid = threadIdx.x;
    const int lane = tid & 31, wid = tid >> 5;       // 16 warps
    const int wm = wid & 3, wn = wid >> 2;           // 4 x 4 warp grid
    const int g4 = lane >> 2, tq = lane & 3;
    const int lr = tid >> 2;                          // loader row 0..127
    const int q4 = tid & 3;                           // loader quarter

    const int Kc = Kp >> 6;      // 64-wide chunks per plane
    const int NC = c1 - c0;

    // ldmatrix lane-address components (x4: rows of two 8x8 pairs + klo/khi)
    const uint32_t a_off = (uint32_t)(wm * 32 + ((lane >> 3) & 1) * 8 + (lane & 7)) * ROWB
                           + ((lane >> 4) & 1) * 16;
    const uint32_t b_off = (uint32_t)(wn * 32 + ((lane >> 4) & 1) * 8 + (lane & 7)) * ROWB
                           + ((lane >> 3) & 1) * 16;

    float acc[2][4][4];
#pragma unroll
    for (int t = 0; t < 2; t++)
#pragma unroll
        for (int nt = 0; nt < 4; nt++)
#pragma unroll
            for (int i = 0; i < 4; i++) acc[t][nt][i] = 0.0f;

    auto issue = [&](int c, int st) {
        int pk = c / Kc;
        int cb = (c - pk * Kc) << 6;
        const __nv_bfloat16* As = ((pk == 1) ? Alo : Ahi)
                                  + (size_t)(n0 + lr) * sA + cb + q4 * 16;
        const __nv_bfloat16* Bs = B + (size_t)lr * ldb + (c << 6) + q4 * 16;
        uint32_t ab = sbase + st * STAGEB + lr * ROWB + q4 * 32;
        uint32_t bb = ab + TILEB;
#pragma unroll
        for (int i = 0; i < 2; i++) {
            cp16(ab + i * 16, As + i * 8);
            cp16(bb + i * 16, Bs + i * 8);
        }
        cp_commit();
    };

    issue(c0, 0);
    if (NC > 1) issue(c0 + 1, 1); else cp_commit();

    for (int ci = 0; ci < NC; ci++) {
        cp_wait1();
        __syncthreads();

        const uint32_t sa = sbase + (ci % 3) * STAGEB;
        const uint32_t aaddr = sa + a_off;
        const uint32_t baddr = sa + TILEB + b_off;
#pragma unroll
        for (int kk = 0; kk < 4; kk++) {
            uint32_t a[2][4], b[2][4];
            ldsm_x4(a[0], aaddr + kk * 32);
            ldsm_x4(a[1], aaddr + 16 * ROWB + kk * 32);
            ldsm_x4(b[0], baddr + kk * 32);
            ldsm_x4(b[1], baddr + 16 * ROWB + kk * 32);
#pragma unroll
            for (int nt = 0; nt < 4; nt++) {
                mma16816(acc[0][nt], a[0], b[nt >> 1] + (nt & 1) * 2);
                mma16816(acc[1][nt], a[1], b[nt >> 1] + (nt & 1) * 2);
            }
        }

        if (ci + 2 < NC) issue(c0 + ci + 2, (ci + 2) % 3);
        else cp_commit();   // empty group keeps wait_group bookkeeping consistent
    }

#pragma unroll
    for (int t = 0; t < 2; t++)
#pragma unroll
        for (int nt = 0; nt < 4; nt++) {
            int gm = n0 + wm * 32 + t * 16 + g4;
            int gn = wn * 32 + nt * 8 + tq * 2;
            float bx = 0.0f, by = 0.0f;
            if (bias) { bx = __ldg(bias + gn); by = __ldg(bias + gn + 1); }
            float2 v0 = make_float2(acc[t][nt][0] + bx, acc[t][nt][1] + by);
            float2 v1 = make_float2(acc[t][nt][2] + bx, acc[t][nt][3] + by);
            *(float2*)(C + (size_t)gm * ldc + gn) = v0;
            *(float2*)(C + (size_t)(gm + 8) * ldc + gn) = v1;
        }
}

// ---------------------------------------------------------------------------
// Kernel 1: QKV projections. V segs (s<3) split in K over blockIdx.z:
// z=0 -> chunks [0,38) into g_qkv; z=1 -> chunks [38,75) into g_qkv2.
// ---------------------------------------------------------------------------
__global__ __launch_bounds__(512, 2)
void qkv_mma_kernel() {
    const int Fps[9] = {1600,1600,1600, 384,384,384, 128,128,128};
    const int ub[9]  = { 512, 512, 512, 128,128,128,   0,  0,  0};
    const int s = blockIdx.y, z = blockIdx.z;
    const int Fp = Fps[s];
    const int NC = 3 * (Fp >> 6);

    int c0 = 0, c1 = NC, ldc = 1152;
    float* C = g_qkv + s * 128;
    if (s < 3) {
        if (z == 0) c1 = 38;
        else { c0 = 38; C = g_qkv2 + s * 128; ldc = 384; }
    } else if (z == 1) {
        return;
    }
    gemm_bf16_128(g_h_hi + ub[s], g_h_lo + ub[s], HW, Fp,
                  g_ws + (size_t)s * 128 * 4800, 3 * Fp,
                  C, ldc, nullptr, blockIdx.x * 128, c0, c1);
}

// ---------------------------------------------------------------------------
// Kernel 2: attention, one 128-thread block per (n, u); 4 warps = row stripes.
// Sequential loop over 4 column-quarters; per quarter the same register-
// resident XOR-butterfly as R12. Row output accumulates in a register across
// quarters; att hi/lo written directly (no partial buffer, no fixup kernel).
// q loaded once; k/v loaded per quarter; Z assembled via tiny smem array.
// ---------------------------------------------------------------------------
__global__ __launch_bounds__(128)
void attn_kernel() {
    __shared__ float zp[4][32];    // [stripe][col-in-quarter] Z partials

    const int n = blockIdx.x;
    const int u = blockIdx.y;      // 0=V, 1=A, 2=T (qkv seg order)
    const int t    = threadIdx.x;
    const int lane = t & 31;
    const int ih   = t >> 5;       // row stripe [ih*32, +32)

    const float* base  = g_qkv  + (size_t)n * 1152 + u * 384;
    const float* base2 = g_qkv2 + (size_t)n * 384;

    // log2(e) / sqrt(128)
    const float scale = 1.4426950408889634f / 11.313708498984761f;
    const int row = ih * 32 + lane;
    float qraw = base[row];
    if (u == 0) qraw += base2[row];
    const float qown = qraw * scale;

    float out = 0.0f;
#pragma unroll 1
    for (int jq = 0; jq < 4; jq++) {
        const int kj = jq * 32 + lane;
        float kraw = base[128 + kj];
        float vraw = base[256 + kj];
        if (u == 0) {
            kraw += base2[128 + kj];
            vraw += base2[256 + kj];
        }

        // Phase 1: c[s] = E[stripe row (lane^s)][col kj], lane-local column Z.
        float c[32];
        float z = 0.0f;
#pragma unroll
        for (int s = 0; s < 32; s++) {
            float qi = __shfl_xor_sync(0xFFFFFFFFu, qown, s);
            float e = ex2f(qi * kraw);
            c[s] = e;
            z += e;
        }
        zp[ih][lane] = z;
        __syncthreads();

        // Column Z over all 4 stripes; lane-local w_j = v_j / Z_j
        float Z = (zp[0][lane] + zp[1][lane]) + (zp[2][lane] + zp[3][lane]);
        const float ws = vraw / Z;

        // Phase 2: butterfly transpose-sum -> this quarter's row partial.
        float o = 0.0f;
#pragma unroll
        for (int s = 0; s < 32; s++) {
            o += __shfl_xor_sync(0xFFFFFFFFu, c[s] * ws, s);
        }
        out += o;
        __syncthreads();   // zp reused next quarter
    }

    const int attoff = (2 - u) * 128;   // att layout [T|A|V]
    __nv_bfloat16 hi = __float2bfloat16(out);
    g_att_hi[(size_t)n * 384 + attoff + row] = hi;
    g_att_lo[(size_t)n * 384 + attoff + row] = __float2bfloat16(out - __bfloat162float(hi));
}

// ---------------------------------------------------------------------------
// Kernel 3: out = att @ Wln.T + bln (plain bf16 GEMM, K' = 1152)
// ---------------------------------------------------------------------------
__global__ __launch_bounds__(512, 2)
void out_mma_kernel(const float* __restrict__ bln, float* __restrict__ out) {
    gemm_bf16_128(g_att_hi, g_att_lo, 384, 384, g_wln, 1152,
                  out, 128, bln, blockIdx.x * 128, 0, 18);
}

// ---------------------------------------------------------------------------
// Input order: 0 g, 1 h, 2 WqT, 3 WkT, 4 WvT, 5 WqA, 6 WkA, 7 WvA,
//              8 WqV, 9 WkV, 10 WvV, 11 Wln, 12 bln
// ---------------------------------------------------------------------------
extern "C" void kernel_launch(void* const* d_in, const int* in_sizes, int n_in,
                              void* d_out, int out_size) {
    const float* h = (const float*)d_in[1];
    WPtrs wp;
    wp.w[0] = (const float*)d_in[8];   // WqV
    wp.w[1] = (const float*)d_in[9];   // WkV
    wp.w[2] = (const float*)d_in[10];  // WvV
    wp.w[3] = (const float*)d_in[5];   // WqA
    wp.w[4] = (const float*)d_in[6];   // WkA
    wp.w[5] = (const float*)d_in[7];   // WvA
    wp.w[6] = (const float*)d_in[2];   // WqT
    wp.w[7] = (const float*)d_in[3];   // WkT
    wp.w[8] = (const float*)d_in[4];   // WvT
    const float* Wln = (const float*)d_in[11];
    const float* bln = (const float*)d_in[12];

    conv_h_kernel<<<NROWS, 256>>>(h);
    conv_w_kernel<<<dim3(128, 10), 256>>>(wp, Wln);

    cudaFuncSetAttribute(qkv_mma_kernel, cudaFuncAttributeMaxDynamicSharedMemorySize,
                         GEMM_SMEM);
    qkv_mma_kernel<<<dim3(64, 9, 2), 512, GEMM_SMEM>>>();

    attn_kernel<<<dim3(NROWS, 3), 128>>>();

    cudaFuncSetAttribute(out_mma_kernel, cudaFuncAttributeMaxDynamicSharedMemorySize,
                         GEMM_SMEM);
    out_mma_kernel<<<64, 512, GEMM_SMEM>>>(bln, (float*)d_out);
}

// round 15
// speedup vs baseline: 1.3219x; 1.1975x over previous
#include <cuda_runtime.h>
#include <cuda_fp16.h>
#include <cuda_bf16.h>
#include <cstdint>
#include <cstddef>

#define NROWS 8192
#define INDIM 2029
#define HW 2112   // padded plane width: 128(T) + 384(A) + 1600(V)

// Scratch (device globals — no allocation allowed)
__device__ __align__(16) __half g_h_hi[NROWS * HW];
__device__ __align__(16) __half g_h_lo[NROWS * HW];
__device__ __align__(16) __half g_ws[9 * 128 * 1600];    // per-seg single bh plane (stride 1600)
__device__ __align__(16) __half g_wln[128 * 384];        // Wln bh plane
__device__ float g_qkv[NROWS * 1152];                    // [n][Vq Vk Vv Aq Ak Av Tq Tk Tv]
__device__ float g_qkv2[NROWS * 384];                    // V segs, upper-K partial
__device__ __align__(16) __half g_att_hi[NROWS * 384];   // [n][T|A|V] hi
__device__ __align__(16) __half g_att_lo[NROWS * 384];   // [n][T|A|V] lo

struct WPtrs { const float* w[9]; };

__device__ __forceinline__ float ex2f(float x) {
    float r; asm("ex2.approx.f32 %0, %1;" : "=f"(r) : "f"(x)); return r;
}
__device__ __forceinline__ uint32_t smem_u32(const void* p) {
    uint32_t a;
    asm("{ .reg .u64 t; cvta.to.shared.u64 t, %1; cvt.u32.u64 %0, t; }" : "=r"(a) : "l"(p));
    return a;
}
__device__ __forceinline__ void mma16816(float* c, const uint32_t* a, const uint32_t* b) {
    asm volatile(
        "mma.sync.aligned.m16n8k16.row.col.f32.f16.f16.f32 "
        "{%0,%1,%2,%3}, {%4,%5,%6,%7}, {%8,%9}, {%0,%1,%2,%3};"
        : "+f"(c[0]), "+f"(c[1]), "+f"(c[2]), "+f"(c[3])
        : "r"(a[0]), "r"(a[1]), "r"(a[2]), "r"(a[3]), "r"(b[0]), "r"(b[1]));
}
__device__ __forceinline__ void ldsm_x4(uint32_t* r, uint32_t addr) {
    asm volatile("ldmatrix.sync.aligned.m8n8.x4.shared.b16 {%0,%1,%2,%3}, [%4];"
        : "=r"(r[0]), "=r"(r[1]), "=r"(r[2]), "=r"(r[3]) : "r"(addr));
}
__device__ __forceinline__ void cp16(uint32_t d, const void* s) {
    asm volatile("cp.async.cg.shared.global [%0], [%1], 16;" :: "r"(d), "l"(s));
}
__device__ __forceinline__ void cp_commit() { asm volatile("cp.async.commit_group;" ::: "memory"); }
__device__ __forceinline__ void cp_wait1()  { asm volatile("cp.async.wait_group 1;" ::: "memory"); }

// ---------------------------------------------------------------------------
// Precompute: h -> per-unit fp16 hi/lo planes (zero-padded widths 128/384/1600)
// ---------------------------------------------------------------------------
__global__ __launch_bounds__(256)
void conv_h_kernel(const float* __restrict__ h) {
    const int n = blockIdx.x;
    const float* hrow = h + (size_t)n * INDIM;
    for (int g = threadIdx.x; g < HW / 4; g += 256) {
        const int col = g * 4;
        int off, local0, F;
        if (col < 128)      { off = 0;   local0 = col;       F = 100; }
        else if (col < 512) { off = 100; local0 = col - 128; F = 342; }
        else                { off = 442; local0 = col - 512; F = 1587; }
        __half hi4[4], lo4[4];
#pragma unroll
        for (int e = 0; e < 4; e++) {
            int lc = local0 + e;
            float v = (lc < F) ? __ldg(hrow + off + lc) : 0.0f;
            __half hi = __float2half(v);
            hi4[e] = hi;
            lo4[e] = __float2half(v - __half2float(hi));
        }
        *reinterpret_cast<uint2*>(&g_h_hi[(size_t)n * HW + col]) = *reinterpret_cast<uint2*>(hi4);
        *reinterpret_cast<uint2*>(&g_h_lo[(size_t)n * HW + col]) = *reinterpret_cast<uint2*>(lo4);
    }
}

// ---------------------------------------------------------------------------
// Precompute weights: single fp16 bh plane per seg (and Wln as seg 9)
// ---------------------------------------------------------------------------
__global__ __launch_bounds__(256)
void conv_w_kernel(WPtrs wp, const float* __restrict__ Wln) {
    const int Fs[10]  = {1587,1587,1587, 342,342,342, 100,100,100, 384};
    const int Fps[10] = {1600,1600,1600, 384,384,384, 128,128,128, 384};
    const int d = blockIdx.x, t = blockIdx.y;
    const int F = Fs[t], Fp = Fps[t];
    const float* W = (t < 9) ? wp.w[t] : Wln;
    __half* dst = (t < 9) ? (g_ws + (size_t)t * 128 * 1600 + (size_t)d * Fp)
                          : (g_wln + (size_t)d * 384);
    for (int k = threadIdx.x; k < Fp; k += 256) {
        float v = (k < F) ? __ldg(W + (size_t)d * F + k) : 0.0f;
        dst[k] = __float2half(v);
    }
}

// ---------------------------------------------------------------------------
// fp16 2-pass GEMM, 512 threads: C[128x128] = (Ah+Al)[128x Kp] * Bh[128x Kp]^T
// (+ bias), over chunk range [c0, c1) of NC = 2*Kc chunks (pass 0: Ah, pass 1:
// Al; B plane shared). 16 warps, warp tile 32x32; cp.async 3-stage pipeline,
// ldmatrix fragments, smem row stride 144B.
// ---------------------------------------------------------------------------
#define ROWB 144
#define TILEB (128 * ROWB)
#define STAGEB (2 * TILEB)
#define GEMM_SMEM (3 * STAGEB)   // 110592

__device__ __forceinline__ void gemm_fp16_128(
    const __half* __restrict__ Ahi, const __half* __restrict__ Alo,
    int sA, int Kp,
    const __half* __restrict__ B, int ldb,
    float* __restrict__ C, int ldc, const float* __restrict__ bias, int n0,
    int c0, int c1)
{
    extern __shared__ __align__(16) char dsm[];
    const uint32_t sbase = smem_u32(dsm);
    const int tid = threadIdx.x;
    const int lane = tid & 31, wid = tid >> 5;       // 16 warps
    const int wm = wid & 3, wn = wid >> 2;           // 4 x 4 warp grid
    const int g4 = lane >> 2, tq = lane & 3;
    const int lr = tid >> 2;                          // loader row 0..127
    const int q4 = tid & 3;                           // loader quarter

    const int Kc = Kp >> 6;      // 64-wide chunks per plane
    const int NC = c1 - c0;

    // ldmatrix lane-address components
    const uint32_t a_off = (uint32_t)(wm * 32 + ((lane >> 3) & 1) * 8 + (lane & 7)) * ROWB
                           + ((lane >> 4) & 1) * 16;
    const uint32_t b_off = (uint32_t)(wn * 32 + ((lane >> 4) & 1) * 8 + (lane & 7)) * ROWB
                           + ((lane >> 3) & 1) * 16;

    float acc[2][4][4];
#pragma unroll
    for (int t = 0; t < 2; t++)
#pragma unroll
        for (int nt = 0; nt < 4; nt++)
#pragma unroll
            for (int i = 0; i < 4; i++) acc[t][nt][i] = 0.0f;

    auto issue = [&](int c, int st) {
        int pk = c / Kc;                        // 0 -> Ah, 1 -> Al
        int cb = (c - pk * Kc) << 6;            // column base (shared by A and B)
        const __half* As = ((pk == 1) ? Alo : Ahi)
                           + (size_t)(n0 + lr) * sA + cb + q4 * 16;
        const __half* Bs = B + (size_t)lr * ldb + cb + q4 * 16;
        uint32_t ab = sbase + st * STAGEB + lr * ROWB + q4 * 32;
        uint32_t bb = ab + TILEB;
#pragma unroll
        for (int i = 0; i < 2; i++) {
            cp16(ab + i * 16, As + i * 8);
            cp16(bb + i * 16, Bs + i * 8);
        }
        cp_commit();
    };

    issue(c0, 0);
    if (NC > 1) issue(c0 + 1, 1); else cp_commit();

    for (int ci = 0; ci < NC; ci++) {
        cp_wait1();
        __syncthreads();

        const uint32_t sa = sbase + (ci % 3) * STAGEB;
        const uint32_t aaddr = sa + a_off;
        const uint32_t baddr = sa + TILEB + b_off;
#pragma unroll
        for (int kk = 0; kk < 4; kk++) {
            uint32_t a[2][4], b[2][4];
            ldsm_x4(a[0], aaddr + kk * 32);
            ldsm_x4(a[1], aaddr + 16 * ROWB + kk * 32);
            ldsm_x4(b[0], baddr + kk * 32);
            ldsm_x4(b[1], baddr + 16 * ROWB + kk * 32);
#pragma unroll
            for (int nt = 0; nt < 4; nt++) {
                mma16816(acc[0][nt], a[0], b[nt >> 1] + (nt & 1) * 2);
                mma16816(acc[1][nt], a[1], b[nt >> 1] + (nt & 1) * 2);
            }
        }

        if (ci + 2 < NC) issue(c0 + ci + 2, (ci + 2) % 3);
        else cp_commit();   // empty group keeps wait_group bookkeeping consistent
    }

#pragma unroll
    for (int t = 0; t < 2; t++)
#pragma unroll
        for (int nt = 0; nt < 4; nt++) {
            int gm = n0 + wm * 32 + t * 16 + g4;
            int gn = wn * 32 + nt * 8 + tq * 2;
            float bx = 0.0f, by = 0.0f;
            if (bias) { bx = __ldg(bias + gn); by = __ldg(bias + gn + 1); }
            float2 v0 = make_float2(acc[t][nt][0] + bx, acc[t][nt][1] + by);
            float2 v1 = make_float2(acc[t][nt][2] + bx, acc[t][nt][3] + by);
            *(float2*)(C + (size_t)gm * ldc + gn) = v0;
            *(float2*)(C + (size_t)(gm + 8) * ldc + gn) = v1;
        }
}

// ---------------------------------------------------------------------------
// Kernel 1: QKV projections. NC = 2*Kc chunks per seg (V: 50, A: 12, T: 4).
// V segs (s<3) split over blockIdx.z: z=0 -> chunks [0,25) into g_qkv;
// z=1 -> chunks [25,50) into g_qkv2.
// ---------------------------------------------------------------------------
__global__ __launch_bounds__(512, 2)
void qkv_mma_kernel() {
    const int Fps[9] = {1600,1600,1600, 384,384,384, 128,128,128};
    const int ub[9]  = { 512, 512, 512, 128,128,128,   0,  0,  0};
    const int s = blockIdx.y, z = blockIdx.z;
    const int Fp = Fps[s];
    const int NC = 2 * (Fp >> 6);

    int c0 = 0, c1 = NC, ldc = 1152;
    float* C = g_qkv + s * 128;
    if (s < 3) {
        if (z == 0) c1 = 25;
        else { c0 = 25; C = g_qkv2 + s * 128; ldc = 384; }
    } else if (z == 1) {
        return;
    }
    gemm_fp16_128(g_h_hi + ub[s], g_h_lo + ub[s], HW, Fp,
                  g_ws + (size_t)s * 128 * 1600, Fp,
                  C, ldc, nullptr, blockIdx.x * 128, c0, c1);
}

// ---------------------------------------------------------------------------
// Kernel 2: attention, one 128-thread block per (n, u); 4 warps = row stripes.
// Sequential loop over 4 column-quarters; register-resident XOR-butterfly per
// 32x32 E block. Row output accumulates in registers; att hi/lo (fp16) written
// directly. 4-way partial accumulators break the z/out FADD chains.
// ---------------------------------------------------------------------------
__global__ __launch_bounds__(128)
void attn_kernel() {
    __shared__ float zp[4][32];    // [stripe][col-in-quarter] Z partials

    const int n = blockIdx.x;
    const int u = blockIdx.y;      // 0=V, 1=A, 2=T (qkv seg order)
    const int t    = threadIdx.x;
    const int lane = t & 31;
    const int ih   = t >> 5;       // row stripe [ih*32, +32)

    const float* base  = g_qkv  + (size_t)n * 1152 + u * 384;
    const float* base2 = g_qkv2 + (size_t)n * 384;

    // log2(e) / sqrt(128)
    const float scale = 1.4426950408889634f / 11.313708498984761f;
    const int row = ih * 32 + lane;
    float qraw = base[row];
    if (u == 0) qraw += base2[row];
    const float qown = qraw * scale;

    float out0 = 0.0f, out1 = 0.0f, out2 = 0.0f, out3 = 0.0f;
#pragma unroll 1
    for (int jq = 0; jq < 4; jq++) {
        const int kj = jq * 32 + lane;
        float kraw = base[128 + kj];
        float vraw = base[256 + kj];
        if (u == 0) {
            kraw += base2[128 + kj];
            vraw += base2[256 + kj];
        }

        // Phase 1: c[s] = E[stripe row (lane^s)][col kj], 4-way column-Z partials.
        float c[32];
        float z0 = 0.0f, z1 = 0.0f, z2 = 0.0f, z3 = 0.0f;
#pragma unroll
        for (int s = 0; s < 32; s += 4) {
            float e0 = ex2f(__shfl_xor_sync(0xFFFFFFFFu, qown, s + 0) * kraw);
            float e1 = ex2f(__shfl_xor_sync(0xFFFFFFFFu, qown, s + 1) * kraw);
            float e2 = ex2f(__shfl_xor_sync(0xFFFFFFFFu, qown, s + 2) * kraw);
            float e3 = ex2f(__shfl_xor_sync(0xFFFFFFFFu, qown, s + 3) * kraw);
            c[s + 0] = e0; c[s + 1] = e1; c[s + 2] = e2; c[s + 3] = e3;
            z0 += e0; z1 += e1; z2 += e2; z3 += e3;
        }
        zp[ih][lane] = (z0 + z1) + (z2 + z3);
        __syncthreads();

        // Column Z over all 4 stripes; lane-local w_j = v_j / Z_j
        float Z = (zp[0][lane] + zp[1][lane]) + (zp[2][lane] + zp[3][lane]);
        const float ws = vraw / Z;

        // Phase 2: butterfly transpose-sum, 4-way accumulators.
#pragma unroll
        for (int s = 0; s < 32; s += 4) {
            out0 += __shfl_xor_sync(0xFFFFFFFFu, c[s + 0] * ws, s + 0);
            out1 += __shfl_xor_sync(0xFFFFFFFFu, c[s + 1] * ws, s + 1);
            out2 += __shfl_xor_sync(0xFFFFFFFFu, c[s + 2] * ws, s + 2);
            out3 += __shfl_xor_sync(0xFFFFFFFFu, c[s + 3] * ws, s + 3);
        }
        __syncthreads();   // zp reused next quarter
    }
    float out = (out0 + out1) + (out2 + out3);

    const int attoff = (2 - u) * 128;   // att layout [T|A|V]
    __half hi = __float2half(out);
    g_att_hi[(size_t)n * 384 + attoff + row] = hi;
    g_att_lo[(size_t)n * 384 + attoff + row] = __float2half(out - __half2float(hi));
}

// ---------------------------------------------------------------------------
// Kernel 3: out = att @ Wln.T + bln (fp16 2-pass GEMM, NC = 12)
// ---------------------------------------------------------------------------
__global__ __launch_bounds__(512, 2)
void out_mma_kernel(const float* __restrict__ bln, float* __restrict__ out) {
    gemm_fp16_128(g_att_hi, g_att_lo, 384, 384, g_wln, 384,
                  out, 128, bln, blockIdx.x * 128, 0, 12);
}

// ---------------------------------------------------------------------------
// Input order: 0 g, 1 h, 2 WqT, 3 WkT, 4 WvT, 5 WqA, 6 WkA, 7 WvA,
//              8 WqV, 9 WkV, 10 WvV, 11 Wln, 12 bln
// ---------------------------------------------------------------------------
extern "C" void kernel_launch(void* const* d_in, const int* in_sizes, int n_in,
                              void* d_out, int out_size) {
    const float* h = (const float*)d_in[1];
    WPtrs wp;
    wp.w[0] = (const float*)d_in[8];   // WqV
    wp.w[1] = (const float*)d_in[9];   // WkV
    wp.w[2] = (const float*)d_in[10];  // WvV
    wp.w[3] = (const float*)d_in[5];   // WqA
    wp.w[4] = (const float*)d_in[6];   // WkA
    wp.w[5] = (const float*)d_in[7];   // WvA
    wp.w[6] = (const float*)d_in[2];   // WqT
    wp.w[7] = (const float*)d_in[3];   // WkT
    wp.w[8] = (const float*)d_in[4];   // WvT
    const float* Wln = (const float*)d_in[11];
    const float* bln = (const float*)d_in[12];

    conv_h_kernel<<<NROWS, 256>>>(h);
    conv_w_kernel<<<dim3(128, 10), 256>>>(wp, Wln);

    cudaFuncSetAttribute(qkv_mma_kernel, cudaFuncAttributeMaxDynamicSharedMemorySize,
                         GEMM_SMEM);
    qkv_mma_kernel<<<dim3(64, 9, 2), 512, GEMM_SMEM>>>();

    attn_kernel<<<dim3(NROWS, 3), 128>>>();

    cudaFuncSetAttribute(out_mma_kernel, cudaFuncAttributeMaxDynamicSharedMemorySize,
                         GEMM_SMEM);
    out_mma_kernel<<<64, 512, GEMM_SMEM>>>(bln, (float*)d_out);
}

// round 16
// speedup vs baseline: 1.6158x; 1.2223x over previous
#include <cuda_runtime.h>
#include <cuda_fp16.h>
#include <cstdint>
#include <cstddef>

#define NROWS 8192
#define INDIM 2029
#define HW 2112   // padded plane width: 128(T) + 384(A) + 1600(V)

// Scratch (device globals — no allocation allowed)
__device__ __align__(16) __half g_h_hi[NROWS * HW];
__device__ __align__(16) __half g_h_lo[NROWS * HW];
__device__ __align__(16) __half g_ws[9 * 128 * 1600];    // per-seg single bh plane (stride 1600)
__device__ __align__(16) __half g_wln[128 * 384];        // Wln bh plane
__device__ float g_qkv[NROWS * 1152];                    // [n][Vq Vk Vv Aq Ak Av Tq Tk Tv]
__device__ float g_qkv2[NROWS * 384];                    // V segs, upper-K partial
__device__ __align__(16) __half g_att_hi[NROWS * 384];   // [n][T|A|V] hi
__device__ __align__(16) __half g_att_lo[NROWS * 384];   // [n][T|A|V] lo

struct WPtrs { const float* w[9]; };

__device__ __forceinline__ uint32_t smem_u32(const void* p) {
    uint32_t a;
    asm("{ .reg .u64 t; cvta.to.shared.u64 t, %1; cvt.u32.u64 %0, t; }" : "=r"(a) : "l"(p));
    return a;
}
__device__ __forceinline__ void mma16816(float* c, const uint32_t* a, const uint32_t* b) {
    asm volatile(
        "mma.sync.aligned.m16n8k16.row.col.f32.f16.f16.f32 "
        "{%0,%1,%2,%3}, {%4,%5,%6,%7}, {%8,%9}, {%0,%1,%2,%3};"
        : "+f"(c[0]), "+f"(c[1]), "+f"(c[2]), "+f"(c[3])
        : "r"(a[0]), "r"(a[1]), "r"(a[2]), "r"(a[3]), "r"(b[0]), "r"(b[1]));
}
__device__ __forceinline__ void ldsm_x4(uint32_t* r, uint32_t addr) {
    asm volatile("ldmatrix.sync.aligned.m8n8.x4.shared.b16 {%0,%1,%2,%3}, [%4];"
        : "=r"(r[0]), "=r"(r[1]), "=r"(r[2]), "=r"(r[3]) : "r"(addr));
}
__device__ __forceinline__ void cp16(uint32_t d, const void* s) {
    asm volatile("cp.async.cg.shared.global [%0], [%1], 16;" :: "r"(d), "l"(s));
}
__device__ __forceinline__ void cp_commit() { asm volatile("cp.async.commit_group;" ::: "memory"); }
__device__ __forceinline__ void cp_wait1()  { asm volatile("cp.async.wait_group 1;" ::: "memory"); }

// half2 helpers
__device__ __forceinline__ uint32_t pack_f16x2(float lo, float hi) {
    uint32_t r;
    asm("cvt.rn.f16x2.f32 %0, %1, %2;" : "=r"(r) : "f"(hi), "f"(lo));
    return r;
}
__device__ __forceinline__ uint32_t ex2_f16x2(uint32_t x) {
    uint32_t r;
    asm("ex2.approx.f16x2 %0, %1;" : "=r"(r) : "r"(x));
    return r;
}
__device__ __forceinline__ uint32_t hadd2(uint32_t a, uint32_t b) {
    uint32_t r;
    asm("add.rn.f16x2 %0, %1, %2;" : "=r"(r) : "r"(a), "r"(b));
    return r;
}
__device__ __forceinline__ uint32_t hmul2(uint32_t a, uint32_t b) {
    uint32_t r;
    asm("mul.rn.f16x2 %0, %1, %2;" : "=r"(r) : "r"(a), "r"(b));
    return r;
}
__device__ __forceinline__ void unpack_f16x2(float& lo, float& hi, uint32_t h2) {
    asm("{ .reg .f16 l, h; mov.b32 {l, h}, %2; cvt.f32.f16 %0, l; cvt.f32.f16 %1, h; }"
        : "=f"(lo), "=f"(hi) : "r"(h2));
}

// ---------------------------------------------------------------------------
// Precompute: h -> per-unit fp16 hi/lo planes (zero-padded widths 128/384/1600)
// ---------------------------------------------------------------------------
__global__ __launch_bounds__(256)
void conv_h_kernel(const float* __restrict__ h) {
    const int n = blockIdx.x;
    const float* hrow = h + (size_t)n * INDIM;
    for (int g = threadIdx.x; g < HW / 4; g += 256) {
        const int col = g * 4;
        int off, local0, F;
        if (col < 128)      { off = 0;   local0 = col;       F = 100; }
        else if (col < 512) { off = 100; local0 = col - 128; F = 342; }
        else                { off = 442; local0 = col - 512; F = 1587; }
        __half hi4[4], lo4[4];
#pragma unroll
        for (int e = 0; e < 4; e++) {
            int lc = local0 + e;
            float v = (lc < F) ? __ldg(hrow + off + lc) : 0.0f;
            __half hi = __float2half(v);
            hi4[e] = hi;
            lo4[e] = __float2half(v - __half2float(hi));
        }
        *reinterpret_cast<uint2*>(&g_h_hi[(size_t)n * HW + col]) = *reinterpret_cast<uint2*>(hi4);
        *reinterpret_cast<uint2*>(&g_h_lo[(size_t)n * HW + col]) = *reinterpret_cast<uint2*>(lo4);
    }
}

// ---------------------------------------------------------------------------
// Precompute weights: single fp16 bh plane per seg (and Wln as seg 9)
// ---------------------------------------------------------------------------
__global__ __launch_bounds__(256)
void conv_w_kernel(WPtrs wp, const float* __restrict__ Wln) {
    const int Fs[10]  = {1587,1587,1587, 342,342,342, 100,100,100, 384};
    const int Fps[10] = {1600,1600,1600, 384,384,384, 128,128,128, 384};
    const int d = blockIdx.x, t = blockIdx.y;
    const int F = Fs[t], Fp = Fps[t];
    const float* W = (t < 9) ? wp.w[t] : Wln;
    __half* dst = (t < 9) ? (g_ws + (size_t)t * 128 * 1600 + (size_t)d * Fp)
                          : (g_wln + (size_t)d * 384);
    for (int k = threadIdx.x; k < Fp; k += 256) {
        float v = (k < F) ? __ldg(W + (size_t)d * F + k) : 0.0f;
        dst[k] = __float2half(v);
    }
}

// ---------------------------------------------------------------------------
// fp16 2-pass GEMM, 512 threads: C[128x128] = (Ah+Al)[128x Kp] * Bh[128x Kp]^T
// (+ bias), over chunk range [c0, c1) of NC = 2*Kc chunks (pass 0: Ah, pass 1:
// Al; B plane shared). 16 warps, warp tile 32x32; cp.async 3-stage pipeline,
// ldmatrix fragments, smem row stride 144B.
// ---------------------------------------------------------------------------
#define ROWB 144
#define TILEB (128 * ROWB)
#define STAGEB (2 * TILEB)
#define GEMM_SMEM (3 * STAGEB)   // 110592

__device__ __forceinline__ void gemm_fp16_128(
    const __half* __restrict__ Ahi, const __half* __restrict__ Alo,
    int sA, int Kp,
    const __half* __restrict__ B, int ldb,
    float* __restrict__ C, int ldc, const float* __restrict__ bias, int n0,
    int c0, int c1)
{
    extern __shared__ __align__(16) char dsm[];
    const uint32_t sbase = smem_u32(dsm);
    const int tid = threadIdx.x;
    const int lane = tid & 31, wid = tid >> 5;       // 16 warps
    const int wm = wid & 3, wn = wid >> 2;           // 4 x 4 warp grid
    const int g4 = lane >> 2, tq = lane & 3;
    const int lr = tid >> 2;                          // loader row 0..127
    const int q4 = tid & 3;                           // loader quarter

    const int Kc = Kp >> 6;      // 64-wide chunks per plane
    const int NC = c1 - c0;

    // ldmatrix lane-address components
    const uint32_t a_off = (uint32_t)(wm * 32 + ((lane >> 3) & 1) * 8 + (lane & 7)) * ROWB
                           + ((lane >> 4) & 1) * 16;
    const uint32_t b_off = (uint32_t)(wn * 32 + ((lane >> 4) & 1) * 8 + (lane & 7)) * ROWB
                           + ((lane >> 3) & 1) * 16;

    float acc[2][4][4];
#pragma unroll
    for (int t = 0; t < 2; t++)
#pragma unroll
        for (int nt = 0; nt < 4; nt++)
#pragma unroll
            for (int i = 0; i < 4; i++) acc[t][nt][i] = 0.0f;

    auto issue = [&](int c, int st) {
        int pk = c / Kc;                        // 0 -> Ah, 1 -> Al
        int cb = (c - pk * Kc) << 6;            // column base (shared by A and B)
        const __half* As = ((pk == 1) ? Alo : Ahi)
                           + (size_t)(n0 + lr) * sA + cb + q4 * 16;
        const __half* Bs = B + (size_t)lr * ldb + cb + q4 * 16;
        uint32_t ab = sbase + st * STAGEB + lr * ROWB + q4 * 32;
        uint32_t bb = ab + TILEB;
#pragma unroll
        for (int i = 0; i < 2; i++) {
            cp16(ab + i * 16, As + i * 8);
            cp16(bb + i * 16, Bs + i * 8);
        }
        cp_commit();
    };

    issue(c0, 0);
    if (NC > 1) issue(c0 + 1, 1); else cp_commit();

    for (int ci = 0; ci < NC; ci++) {
        cp_wait1();
        __syncthreads();

        const uint32_t sa = sbase + (ci % 3) * STAGEB;
        const uint32_t aaddr = sa + a_off;
        const uint32_t baddr = sa + TILEB + b_off;
#pragma unroll
        for (int kk = 0; kk < 4; kk++) {
            uint32_t a[2][4], b[2][4];
            ldsm_x4(a[0], aaddr + kk * 32);
            ldsm_x4(a[1], aaddr + 16 * ROWB + kk * 32);
            ldsm_x4(b[0], baddr + kk * 32);
            ldsm_x4(b[1], baddr + 16 * ROWB + kk * 32);
#pragma unroll
            for (int nt = 0; nt < 4; nt++) {
                mma16816(acc[0][nt], a[0], b[nt >> 1] + (nt & 1) * 2);
                mma16816(acc[1][nt], a[1], b[nt >> 1] + (nt & 1) * 2);
            }
        }

        if (ci + 2 < NC) issue(c0 + ci + 2, (ci + 2) % 3);
        else cp_commit();   // empty group keeps wait_group bookkeeping consistent
    }

#pragma unroll
    for (int t = 0; t < 2; t++)
#pragma unroll
        for (int nt = 0; nt < 4; nt++) {
            int gm = n0 + wm * 32 + t * 16 + g4;
            int gn = wn * 32 + nt * 8 + tq * 2;
            float bx = 0.0f, by = 0.0f;
            if (bias) { bx = __ldg(bias + gn); by = __ldg(bias + gn + 1); }
            float2 v0 = make_float2(acc[t][nt][0] + bx, acc[t][nt][1] + by);
            float2 v1 = make_float2(acc[t][nt][2] + bx, acc[t][nt][3] + by);
            *(float2*)(C + (size_t)gm * ldc + gn) = v0;
            *(float2*)(C + (size_t)(gm + 8) * ldc + gn) = v1;
        }
}

// ---------------------------------------------------------------------------
// Kernel 1: QKV projections. NC = 2*Kc chunks per seg (V: 50, A: 12, T: 4).
// V segs (s<3) split over blockIdx.z: z=0 -> chunks [0,25) into g_qkv;
// z=1 -> chunks [25,50) into g_qkv2.
// ---------------------------------------------------------------------------
__global__ __launch_bounds__(512, 2)
void qkv_mma_kernel() {
    const int Fps[9] = {1600,1600,1600, 384,384,384, 128,128,128};
    const int ub[9]  = { 512, 512, 512, 128,128,128,   0,  0,  0};
    const int s = blockIdx.y, z = blockIdx.z;
    const int Fp = Fps[s];
    const int NC = 2 * (Fp >> 6);

    int c0 = 0, c1 = NC, ldc = 1152;
    float* C = g_qkv + s * 128;
    if (s < 3) {
        if (z == 0) c1 = 25;
        else { c0 = 25; C = g_qkv2 + s * 128; ldc = 384; }
    } else if (z == 1) {
        return;
    }
    gemm_fp16_128(g_h_hi + ub[s], g_h_lo + ub[s], HW, Fp,
                  g_ws + (size_t)s * 128 * 1600, Fp,
                  C, ldc, nullptr, blockIdx.x * 128, c0, c1);
}

// ---------------------------------------------------------------------------
// Kernel 2: attention, one 128-thread block per (n, u); 4 warps = row stripes.
// Two outer iterations of 64 columns: lane owns column pair (jA, jB=jA+32)
// packed in half2. XOR-butterfly per 32x32x2 block:
//   phase 1: x in fp32, cvt.rn.f16x2 pack, ONE ex2.approx.f16x2 per 2 exps,
//            4-way half2 Z chains (<=8 terms) -> fp32 stripe partials.
//   phase 2: hmul2 by (wA,wB), 32-bit shfl, 4-way half2 out chains (<=8 terms)
//            -> fp32 accumulator per iteration.
// ---------------------------------------------------------------------------
__global__ __launch_bounds__(128)
void attn_kernel() {
    __shared__ float zpA[4][32];
    __shared__ float zpB[4][32];

    const int n = blockIdx.x;
    const int u = blockIdx.y;      // 0=V, 1=A, 2=T (qkv seg order)
    const int t    = threadIdx.x;
    const int lane = t & 31;
    const int ih   = t >> 5;       // row stripe [ih*32, +32)

    const float* base  = g_qkv  + (size_t)n * 1152 + u * 384;
    const float* base2 = g_qkv2 + (size_t)n * 384;

    // log2(e) / sqrt(128)
    const float scale = 1.4426950408889634f / 11.313708498984761f;
    const int row = ih * 32 + lane;
    float qraw = base[row];
    if (u == 0) qraw += base2[row];
    const float qown = qraw * scale;

    float outF = 0.0f;
#pragma unroll 1
    for (int it = 0; it < 2; it++) {
        const int jA = it * 64 + lane;
        const int jB = jA + 32;
        float kA = base[128 + jA], kB = base[128 + jB];
        float vA = base[256 + jA], vB = base[256 + jB];
        if (u == 0) {
            kA += base2[128 + jA]; kB += base2[128 + jB];
            vA += base2[256 + jA]; vB += base2[256 + jB];
        }

        // Phase 1: packed exp; c[s] = half2(E[r^s][jA], E[r^s][jB])
        uint32_t c[32];
        uint32_t z2[4] = {0u, 0u, 0u, 0u};
#pragma unroll
        for (int s = 0; s < 32; s++) {
            float qi = __shfl_xor_sync(0xFFFFFFFFu, qown, s);
            uint32_t x2 = pack_f16x2(qi * kA, qi * kB);
            uint32_t e2 = ex2_f16x2(x2);
            c[s] = e2;
            z2[s & 3] = hadd2(z2[s & 3], e2);
        }
        uint32_t zt = hadd2(hadd2(z2[0], z2[1]), hadd2(z2[2], z2[3]));
        float zAp, zBp;
        unpack_f16x2(zAp, zBp, zt);
        zpA[ih][lane] = zAp;
        zpB[ih][lane] = zBp;
        __syncthreads();

        float ZA = (zpA[0][lane] + zpA[1][lane]) + (zpA[2][lane] + zpA[3][lane]);
        float ZB = (zpB[0][lane] + zpB[1][lane]) + (zpB[2][lane] + zpB[3][lane]);
        uint32_t ws2 = pack_f16x2(vA / ZA, vB / ZB);

        // Phase 2: butterfly transpose-sum on half2 pairs.
        uint32_t o2[4] = {0u, 0u, 0u, 0u};
#pragma unroll
        for (int s = 0; s < 32; s++) {
            uint32_t prod = hmul2(c[s], ws2);
            uint32_t recv = __shfl_xor_sync(0xFFFFFFFFu, prod, s);
            o2[s & 3] = hadd2(o2[s & 3], recv);
        }
        uint32_t ot = hadd2(hadd2(o2[0], o2[1]), hadd2(o2[2], o2[3]));
        float oA, oB;
        unpack_f16x2(oA, oB, ot);
        outF += oA + oB;
        __syncthreads();   // zp reused next iteration
    }

    const int attoff = (2 - u) * 128;   // att layout [T|A|V]
    __half hi = __float2half(outF);
    g_att_hi[(size_t)n * 384 + attoff + row] = hi;
    g_att_lo[(size_t)n * 384 + attoff + row] = __float2half(outF - __half2float(hi));
}

// ---------------------------------------------------------------------------
// Kernel 3: out = att @ Wln.T + bln (fp16 2-pass GEMM, NC = 12)
// ---------------------------------------------------------------------------
__global__ __launch_bounds__(512, 2)
void out_mma_kernel(const float* __restrict__ bln, float* __restrict__ out) {
    gemm_fp16_128(g_att_hi, g_att_lo, 384, 384, g_wln, 384,
                  out, 128, bln, blockIdx.x * 128, 0, 12);
}

// ---------------------------------------------------------------------------
// Input order: 0 g, 1 h, 2 WqT, 3 WkT, 4 WvT, 5 WqA, 6 WkA, 7 WvA,
//              8 WqV, 9 WkV, 10 WvV, 11 Wln, 12 bln
// ---------------------------------------------------------------------------
extern "C" void kernel_launch(void* const* d_in, const int* in_sizes, int n_in,
                              void* d_out, int out_size) {
    const float* h = (const float*)d_in[1];
    WPtrs wp;
    wp.w[0] = (const float*)d_in[8];   // WqV
    wp.w[1] = (const float*)d_in[9];   // WkV
    wp.w[2] = (const float*)d_in[10];  // WvV
    wp.w[3] = (const float*)d_in[5];   // WqA
    wp.w[4] = (const float*)d_in[6];   // WkA
    wp.w[5] = (const float*)d_in[7];   // WvA
    wp.w[6] = (const float*)d_in[2];   // WqT
    wp.w[7] = (const float*)d_in[3];   // WkT
    wp.w[8] = (const float*)d_in[4];   // WvT
    const float* Wln = (const float*)d_in[11];
    const float* bln = (const float*)d_in[12];

    conv_h_kernel<<<NROWS, 256>>>(h);
    conv_w_kernel<<<dim3(128, 10), 256>>>(wp, Wln);

    cudaFuncSetAttribute(qkv_mma_kernel, cudaFuncAttributeMaxDynamicSharedMemorySize,
                         GEMM_SMEM);
    qkv_mma_kernel<<<dim3(64, 9, 2), 512, GEMM_SMEM>>>();

    attn_kernel<<<dim3(NROWS, 3), 128>>>();

    cudaFuncSetAttribute(out_mma_kernel, cudaFuncAttributeMaxDynamicSharedMemorySize,
                         GEMM_SMEM);
    out_mma_kernel<<<64, 512, GEMM_SMEM>>>(bln, (float*)d_out);
}